// round 3
// baseline (speedup 1.0000x reference)
#include <cuda_runtime.h>
#include <cuda_bf16.h>
#include <math.h>

#define B_   16
#define T_   500
#define D_   512
#define N_   128
#define E_   640
#define H_   1024
#define A_   1024
#define P_   1024
#define V_   10025
#define KIH  1152              // E_ + D_
#define KRO  2176              // H_ + E_ + D_
#define ZH_  0.05f
#define ZC_  0.15f

#define GKT  12                // k-split for gate GEMM partials
#define GKR  (KIH / GKT)       // 96
#define SQT  16                // k-split for s_t partials
#define SKR  (H_ / SQT)        // 64

// ----------------------------- scratch ------------------------------------
__device__ float g_encctx[B_ * T_ * A_];          // enc @ W_enc_ctx^T + b
__device__ float g_invf[B_ * T_];                 // 0.5 * sigmoid(enc @ w_f)
__device__ float g_h[B_ * H_];
__device__ float g_ctx[B_ * D_];
__device__ float g_accum[B_ * T_];
__device__ float g_energy[B_ * T_];
__device__ float g_pgate[GKT * B_ * 3 * H_];      // gate partials [kt][b][3072]
__device__ float g_stp[SQT * B_ * A_];            // s_t partials  [q][b][1024]
__device__ float g_rin[B_ * N_ * KRO];            // [h | emb | ctx] rows
__device__ float g_ro[B_ * N_ * (P_ / 2)];        // post-maxout readout
__device__ float g_wih_t[KIH * 3 * H_];           // W_ih^T (i,g,o only)
__device__ float g_ws_t[H_ * A_];                 // W_s^T
__device__ int   g_lab64;

// ----------------------------- helpers ------------------------------------
__device__ __forceinline__ float fsig(float x) {
    return __fdividef(1.0f, 1.0f + __expf(-x));
}
__device__ __forceinline__ float ftanh(float x) {
    float a = fabsf(x);
    float e = __expf(-2.0f * a);
    float r = __fdividef(1.0f - e, 1.0f + e);
    return copysignf(r, x);
}

// ----------------------------- init ----------------------------------------
__global__ void k_init() {
    int i = blockIdx.x * blockDim.x + threadIdx.x;   // 16384 threads
    if (i < B_ * H_)  g_h[i]     = 0.0f;
    if (i < B_ * D_)  g_ctx[i]   = 0.0f;
    if (i < B_ * T_)  g_accum[i] = 0.0f;
}

// ------------------------ labels dtype detection ---------------------------
// If labels are int64 (little-endian, values < 2^31), every odd 32-bit word of
// the first 2048 words is zero. For int32 labels those words are random ids.
__global__ void k_detect(const int* __restrict__ lab32) {
    int ok = 1;
    for (int i = threadIdx.x; i < 1024; i += blockDim.x)
        if (lab32[2 * i + 1] != 0) ok = 0;
    int all = __syncthreads_and(ok);
    if (threadIdx.x == 0) g_lab64 = all;
}

// ------------------ shifted embedding gather into g_rin --------------------
__global__ void k_gather(const void* __restrict__ labels,
                         const float* __restrict__ embed) {
    int row = blockIdx.x;                  // b*N_ + n
    int n = row & (N_ - 1);
    int b = row >> 7;
    float4* dst = (float4*)(g_rin + (size_t)row * KRO + H_);
    if (n == 0) {
        for (int k = threadIdx.x; k < E_ / 4; k += blockDim.x)
            dst[k] = make_float4(0.f, 0.f, 0.f, 0.f);
        return;
    }
    int idx = b * N_ + n - 1;
    int lab = g_lab64 ? (int)((const long long*)labels)[idx]
                      : ((const int*)labels)[idx];
    if (lab < 0) lab = 0;
    if (lab >= V_) lab = V_ - 1;
    const float4* src = (const float4*)(embed + (size_t)lab * E_);
    for (int k = threadIdx.x; k < E_ / 4; k += blockDim.x) dst[k] = src[k];
}

// -------------------- transposes (coalesced, tiled) ------------------------
// W_ih [4096][1152] -> g_wih_t [1152][3072], dropping the f gate.
__global__ void k_twih(const float* __restrict__ W_ih) {
    __shared__ float tl[32][33];
    int jj0 = blockIdx.x * 32, k0 = blockIdx.y * 32;
    int tx = threadIdx.x, ty = threadIdx.y;
    for (int i = ty; i < 32; i += 8) {
        int jj = jj0 + i;
        int srow = (jj < 1024) ? jj : jj + 1024;   // skip f rows [1024,2048)
        tl[i][tx] = W_ih[(size_t)srow * KIH + k0 + tx];
    }
    __syncthreads();
    for (int i = ty; i < 32; i += 8)
        g_wih_t[(size_t)(k0 + i) * (3 * H_) + jj0 + tx] = tl[tx][i];
}
// W_s [1024][1024] -> g_ws_t [1024][1024]
__global__ void k_tws(const float* __restrict__ W_s) {
    __shared__ float tl[32][33];
    int j0 = blockIdx.x * 32, k0 = blockIdx.y * 32;
    int tx = threadIdx.x, ty = threadIdx.y;
    for (int i = ty; i < 32; i += 8)
        tl[i][tx] = W_s[(size_t)(j0 + i) * H_ + k0 + tx];
    __syncthreads();
    for (int i = ty; i < 32; i += 8)
        g_ws_t[(size_t)(k0 + i) * A_ + j0 + tx] = tl[tx][i];
}

// ----------------------- inverse fertility ---------------------------------
__global__ void __launch_bounds__(256) k_invf(const float* __restrict__ enc,
                                              const float* __restrict__ wf) {
    __shared__ float wsh[D_];
    int tid = threadIdx.x;
    for (int i = tid; i < D_; i += 256) wsh[i] = wf[i];
    __syncthreads();
    int row  = blockIdx.x * 8 + (tid >> 5);
    int lane = tid & 31;
    if (row >= B_ * T_) return;
    const float4* ep = (const float4*)(enc + (size_t)row * D_);
    const float4* wp = (const float4*)wsh;
    float acc = 0.0f;
#pragma unroll
    for (int i = 0; i < 4; i++) {
        float4 e = ep[i * 32 + lane];
        float4 w = wp[i * 32 + lane];
        acc = fmaf(e.x, w.x, fmaf(e.y, w.y, fmaf(e.z, w.z, fmaf(e.w, w.w, acc))));
    }
#pragma unroll
    for (int o = 16; o; o >>= 1) acc += __shfl_down_sync(0xffffffffu, acc, o);
    if (lane == 0) g_invf[row] = 0.5f * fsig(acc);
}

// -------------------- generic fp32 SGEMM C = A·B^T + bias ------------------
// mode 0: plain; mode 1: fused MaxOut(2) (ldc = N/2)
__global__ void __launch_bounds__(256) k_sgemm(const float* __restrict__ A,
                                               const float* __restrict__ Bm,
                                               const float* __restrict__ bias,
                                               float* __restrict__ C,
                                               int M, int N, int K, int ldc,
                                               int mode) {
    __shared__ float As[8][128];
    __shared__ float Bs[8][128];
    int tid = threadIdx.x;
    int row0 = blockIdx.y * 128, col0 = blockIdx.x * 128;
    int tx = tid & 15, ty = tid >> 4;
    float acc[8][8];
#pragma unroll
    for (int i = 0; i < 8; i++)
#pragma unroll
        for (int j = 0; j < 8; j++) acc[i][j] = 0.0f;
    int lr = tid >> 1;
    int lq = (tid & 1) * 4;
    const float* Ap = A  + (size_t)(row0 + lr) * K + lq;
    const float* Bp = Bm + (size_t)(col0 + lr) * K + lq;
    bool avalid = (row0 + lr) < M;
    bool bvalid = (col0 + lr) < N;
    for (int k0 = 0; k0 < K; k0 += 8) {
        float4 av = avalid ? *(const float4*)(Ap + k0) : make_float4(0, 0, 0, 0);
        float4 bv = bvalid ? *(const float4*)(Bp + k0) : make_float4(0, 0, 0, 0);
        As[lq + 0][lr] = av.x; As[lq + 1][lr] = av.y;
        As[lq + 2][lr] = av.z; As[lq + 3][lr] = av.w;
        Bs[lq + 0][lr] = bv.x; Bs[lq + 1][lr] = bv.y;
        Bs[lq + 2][lr] = bv.z; Bs[lq + 3][lr] = bv.w;
        __syncthreads();
#pragma unroll
        for (int k = 0; k < 8; k++) {
            float ar[8], br[8];
            *(float4*)(ar)     = *(const float4*)&As[k][ty * 8];
            *(float4*)(ar + 4) = *(const float4*)&As[k][ty * 8 + 4];
            *(float4*)(br)     = *(const float4*)&Bs[k][tx * 8];
            *(float4*)(br + 4) = *(const float4*)&Bs[k][tx * 8 + 4];
#pragma unroll
            for (int i = 0; i < 8; i++)
#pragma unroll
                for (int j = 0; j < 8; j++)
                    acc[i][j] = fmaf(ar[i], br[j], acc[i][j]);
        }
        __syncthreads();
    }
    if (mode == 0) {
#pragma unroll
        for (int i = 0; i < 8; i++) {
            int m = row0 + ty * 8 + i;
            if (m >= M) break;
#pragma unroll
            for (int j = 0; j < 8; j++) {
                int nn = col0 + tx * 8 + j;
                if (nn < N) C[(size_t)m * ldc + nn] = acc[i][j] + bias[nn];
            }
        }
    } else {
#pragma unroll
        for (int i = 0; i < 8; i++) {
            int m = row0 + ty * 8 + i;
            if (m >= M) break;
#pragma unroll
            for (int p = 0; p < 4; p++) {
                int nn = col0 + tx * 8 + p * 2;
                float v0 = acc[i][p * 2]     + bias[nn];
                float v1 = acc[i][p * 2 + 1] + bias[nn + 1];
                C[(size_t)m * ldc + (nn >> 1)] = fmaxf(v0, v1);
            }
        }
    }
}

// -------------------- per step 1: gate GEMM partials -----------------------
// grid 144 = (jt 0..11) + 12*(kt 0..11); block 256.
// thread -> 4 j cols x 4 b rows; weights read exactly once per step.
__global__ void __launch_bounds__(256) k_gates(int n) {
    __shared__ float s_inp[GKR * B_];          // [k][b]
    int tid = threadIdx.x;
    int jt = blockIdx.x % 12, kt = blockIdx.x / 12;
    int j0 = jt * 256, k0 = kt * GKR;
    for (int idx = tid; idx < GKR * B_; idx += 256) {
        int kl = idx >> 4, b = idx & 15;
        int kg = k0 + kl;
        float v = (kg < E_)
            ? g_rin[(size_t)(b * N_ + n) * KRO + H_ + kg]
            : g_ctx[b * D_ + kg - E_];
        s_inp[kl * B_ + b] = v;
    }
    __syncthreads();
    int jq = tid & 63, bq = tid >> 6;
    int j = j0 + jq * 4, b0 = bq * 4;
    const float4* s4 = (const float4*)s_inp;
    float4 a0 = make_float4(0, 0, 0, 0), a1 = a0, a2 = a0, a3 = a0;
#pragma unroll 4
    for (int kl = 0; kl < GKR; kl++) {
        float4 w  = *(const float4*)&g_wih_t[(size_t)(k0 + kl) * (3 * H_) + j];
        float4 hv = s4[kl * 4 + bq];
        a0.x = fmaf(hv.x, w.x, a0.x); a0.y = fmaf(hv.x, w.y, a0.y);
        a0.z = fmaf(hv.x, w.z, a0.z); a0.w = fmaf(hv.x, w.w, a0.w);
        a1.x = fmaf(hv.y, w.x, a1.x); a1.y = fmaf(hv.y, w.y, a1.y);
        a1.z = fmaf(hv.y, w.z, a1.z); a1.w = fmaf(hv.y, w.w, a1.w);
        a2.x = fmaf(hv.z, w.x, a2.x); a2.y = fmaf(hv.z, w.y, a2.y);
        a2.z = fmaf(hv.z, w.z, a2.z); a2.w = fmaf(hv.z, w.w, a2.w);
        a3.x = fmaf(hv.w, w.x, a3.x); a3.y = fmaf(hv.w, w.y, a3.y);
        a3.z = fmaf(hv.w, w.z, a3.z); a3.w = fmaf(hv.w, w.w, a3.w);
    }
    size_t base = (size_t)kt * (B_ * 3 * H_) + j;
    *(float4*)&g_pgate[base + (size_t)(b0 + 0) * (3 * H_)] = a0;
    *(float4*)&g_pgate[base + (size_t)(b0 + 1) * (3 * H_)] = a1;
    *(float4*)&g_pgate[base + (size_t)(b0 + 2) * (3 * H_)] = a2;
    *(float4*)&g_pgate[base + (size_t)(b0 + 3) * (3 * H_)] = a3;
}

// -------------------- per step 2: reduce gates -> h ------------------------
__global__ void __launch_bounds__(256) k_h(const float* __restrict__ b_ih,
                                           const float* __restrict__ b_hh,
                                           int n) {
    int idx = blockIdx.x * 256 + threadIdx.x;   // 16384
    int b = idx >> 10, k = idx & 1023;
    float gi = 0.f, gg = 0.f, go = 0.f;
#pragma unroll
    for (int kt = 0; kt < GKT; kt++) {
        size_t base = (size_t)kt * (B_ * 3 * H_) + (size_t)b * (3 * H_);
        gi += g_pgate[base + k];
        gg += g_pgate[base + H_ + k];
        go += g_pgate[base + 2 * H_ + k];
    }
    gi += b_ih[k]          + b_hh[k];
    gg += b_ih[2 * H_ + k] + b_hh[2 * H_ + k];
    go += b_ih[3 * H_ + k] + b_hh[3 * H_ + k];
    float c_new = fsig(gi) * ftanh(gg);
    float h_new = fsig(go) * ftanh(c_new);
    float h = ZH_ * g_h[idx] + (1.0f - ZH_) * h_new;
    g_h[idx] = h;
    g_rin[(size_t)(b * N_ + n) * KRO + k] = h;   // s_stacked slot
}

// -------------------- per step 3: s_t partials -----------------------------
// grid 128 = (q 0..15)*8 + jt; block 128 (one j per thread, 16 b accums).
__global__ void __launch_bounds__(128) k_st() {
    __shared__ float hs[SKR * B_];               // [k][b]
    int tid = threadIdx.x;
    int q = blockIdx.x >> 3, jt = blockIdx.x & 7;
    int j = jt * 128 + tid;
    for (int idx = tid; idx < SKR * B_; idx += 128) {
        int b = idx >> 6, kk = idx & 63;
        hs[kk * B_ + b] = g_h[b * H_ + q * SKR + kk];
    }
    __syncthreads();
    const float4* h4 = (const float4*)hs;
    float acc[16];
#pragma unroll
    for (int i = 0; i < 16; i++) acc[i] = 0.0f;
#pragma unroll 4
    for (int kl = 0; kl < SKR; kl++) {
        float w = g_ws_t[(size_t)(q * SKR + kl) * A_ + j];
        float4 h0 = h4[kl * 4 + 0], h1 = h4[kl * 4 + 1];
        float4 h2 = h4[kl * 4 + 2], h3 = h4[kl * 4 + 3];
        acc[0]  = fmaf(w, h0.x, acc[0]);  acc[1]  = fmaf(w, h0.y, acc[1]);
        acc[2]  = fmaf(w, h0.z, acc[2]);  acc[3]  = fmaf(w, h0.w, acc[3]);
        acc[4]  = fmaf(w, h1.x, acc[4]);  acc[5]  = fmaf(w, h1.y, acc[5]);
        acc[6]  = fmaf(w, h1.z, acc[6]);  acc[7]  = fmaf(w, h1.w, acc[7]);
        acc[8]  = fmaf(w, h2.x, acc[8]);  acc[9]  = fmaf(w, h2.y, acc[9]);
        acc[10] = fmaf(w, h2.z, acc[10]); acc[11] = fmaf(w, h2.w, acc[11]);
        acc[12] = fmaf(w, h3.x, acc[12]); acc[13] = fmaf(w, h3.y, acc[13]);
        acc[14] = fmaf(w, h3.z, acc[14]); acc[15] = fmaf(w, h3.w, acc[15]);
    }
#pragma unroll
    for (int b = 0; b < 16; b++)
        g_stp[(size_t)q * (B_ * A_) + b * A_ + j] = acc[b];
}

// -------------------- per step 4: attention energies -----------------------
// grid 256 = b*16 + tt (32 t per block); block 256 (warp -> 4 t).
__global__ void __launch_bounds__(256) k_energy(const int* __restrict__ seqlen,
                                                const float* __restrict__ v_att,
                                                const float* __restrict__ W_fb) {
    __shared__ float s_sh[A_], v_sh[A_], f_sh[A_];
    int tid = threadIdx.x;
    int b = blockIdx.x >> 4, tt = blockIdx.x & 15;
    for (int j = tid; j < A_; j += 256) {
        float a = 0.0f;
#pragma unroll
        for (int q = 0; q < SQT; q++)
            a += g_stp[(size_t)q * (B_ * A_) + b * A_ + j];
        s_sh[j] = a;
        v_sh[j] = v_att[j];
        f_sh[j] = W_fb[j];
    }
    __syncthreads();
    int w = tid >> 5, lane = tid & 31;
    int t0 = tt * 32 + w * 4;
    int Tb = seqlen[b];
    float eacc[4] = {0.f, 0.f, 0.f, 0.f};
    float abt[4];
#pragma unroll
    for (int i = 0; i < 4; i++)
        abt[i] = (t0 + i < T_) ? g_accum[b * T_ + t0 + i] : 0.0f;
    const float4* s4 = (const float4*)s_sh;
    const float4* v4 = (const float4*)v_sh;
    const float4* f4 = (const float4*)f_sh;
    const float4* ec = (const float4*)g_encctx;
#pragma unroll
    for (int kk = 0; kk < 8; kk++) {
        float4 sv = s4[kk * 32 + lane];
        float4 fv = f4[kk * 32 + lane];
        float4 vv = v4[kk * 32 + lane];
#pragma unroll
        for (int i = 0; i < 4; i++) {
            int t = t0 + i;
            if (t >= T_) continue;
            float4 e = ec[(size_t)(b * T_ + t) * 256 + kk * 32 + lane];
            float a = abt[i];
            eacc[i] += vv.x * ftanh(e.x + sv.x + a * fv.x);
            eacc[i] += vv.y * ftanh(e.y + sv.y + a * fv.y);
            eacc[i] += vv.z * ftanh(e.z + sv.z + a * fv.z);
            eacc[i] += vv.w * ftanh(e.w + sv.w + a * fv.w);
        }
    }
#pragma unroll
    for (int i = 0; i < 4; i++) {
#pragma unroll
        for (int o = 16; o; o >>= 1)
            eacc[i] += __shfl_down_sync(0xffffffffu, eacc[i], o);
        int t = t0 + i;
        if (lane == 0 && t < T_)
            g_energy[b * T_ + t] = (t < Tb) ? eacc[i] : -1e30f;
    }
}

// ------------- per step 5: softmax + context + accum update ----------------
// grid 64 = b*4 + chunk; block 256.
__global__ void __launch_bounds__(256) k_ctxsm(const float* __restrict__ enc,
                                               int n) {
    __shared__ float w_sh[512];
    __shared__ float red[256];
    int tid = threadIdx.x;
    int b = blockIdx.x >> 2, chunk = blockIdx.x & 3;
    // softmax
    float m = -1e30f;
    for (int t = tid; t < T_; t += 256) m = fmaxf(m, g_energy[b * T_ + t]);
    red[tid] = m; __syncthreads();
    for (int o = 128; o; o >>= 1) {
        if (tid < o) red[tid] = fmaxf(red[tid], red[tid + o]);
        __syncthreads();
    }
    float mx = red[0]; __syncthreads();
    float s = 0.0f;
    for (int t = tid; t < T_; t += 256) {
        float e = __expf(g_energy[b * T_ + t] - mx);
        w_sh[t] = e;
        s += e;
    }
    red[tid] = s; __syncthreads();
    for (int o = 128; o; o >>= 1) {
        if (tid < o) red[tid] += red[tid + o];
        __syncthreads();
    }
    float inv = __fdividef(1.0f, red[0]); __syncthreads();
    for (int t = tid; t < T_; t += 256) w_sh[t] *= inv;
    __syncthreads();
    // context over this 128-column chunk
    int dl = tid & 127, half = tid >> 7;
    int d = chunk * 128 + dl;
    float acc = 0.0f;
    for (int t = half; t < T_; t += 2)
        acc = fmaf(w_sh[t], enc[(size_t)(b * T_ + t) * D_ + d], acc);
    red[tid] = acc; __syncthreads();
    if (tid < 128) {
        float v = red[tid] + red[tid + 128];
        g_ctx[b * D_ + d] = v;
        g_rin[(size_t)(b * N_ + n) * KRO + H_ + E_ + d] = v;  // ctx_stacked
    }
    // fertility accumulator (once per b)
    if (chunk == 0)
        for (int t = tid; t < T_; t += 256)
            g_accum[b * T_ + t] += w_sh[t] * g_invf[b * T_ + t];
}

// ----------------------------- launch --------------------------------------
extern "C" void kernel_launch(void* const* d_in, const int* in_sizes, int n_in,
                              void* d_out, int out_size) {
    const float* enc     = (const float*)d_in[0];
    const void*  labels  =               d_in[1];
    const int*   seqlen  = (const int*)  d_in[2];
    const float* embed   = (const float*)d_in[3];
    const float* W_ih    = (const float*)d_in[4];
    const float* b_ih    = (const float*)d_in[5];
    const float* b_hh    = (const float*)d_in[6];
    const float* W_s     = (const float*)d_in[7];
    const float* W_encc  = (const float*)d_in[8];
    const float* b_encc  = (const float*)d_in[9];
    const float* v_att   = (const float*)d_in[10];
    const float* W_invf  = (const float*)d_in[11];
    const float* W_fb    = (const float*)d_in[12];
    const float* W_ro    = (const float*)d_in[13];
    const float* b_ro    = (const float*)d_in[14];
    const float* W_out   = (const float*)d_in[15];
    const float* b_out   = (const float*)d_in[16];
    float* out = (float*)d_out;

    float* encctx; cudaGetSymbolAddress((void**)&encctx, g_encctx);
    float* rin;    cudaGetSymbolAddress((void**)&rin,    g_rin);
    float* ro;     cudaGetSymbolAddress((void**)&ro,     g_ro);

    k_init<<<64, 256>>>();
    k_detect<<<1, 256>>>((const int*)labels);
    k_gather<<<B_ * N_, 160>>>(labels, embed);
    { dim3 blk(32, 8); k_twih<<<dim3(96, 36), blk>>>(W_ih); }
    { dim3 blk(32, 8); k_tws <<<dim3(32, 32), blk>>>(W_s);  }
    k_invf<<<(B_ * T_ + 7) / 8, 256>>>(enc, W_invf);
    k_sgemm<<<dim3(A_ / 128, (B_ * T_ + 127) / 128), 256>>>(
        enc, W_encc, b_encc, encctx, B_ * T_, A_, D_, A_, 0);

    for (int n = 0; n < N_; n++) {
        k_gates <<<144, 256>>>(n);
        k_h     <<<64, 256>>>(b_ih, b_hh, n);
        k_st    <<<128, 128>>>();
        k_energy<<<256, 256>>>(seqlen, v_att, W_fb);
        k_ctxsm <<<64, 256>>>(enc, n);
    }

    // readout (+MaxOut) then vocab projection
    k_sgemm<<<dim3(P_ / 128, (B_ * N_) / 128), 256>>>(
        rin, W_ro, b_ro, ro, B_ * N_, P_, KRO, P_ / 2, 1);
    k_sgemm<<<dim3((V_ + 127) / 128, (B_ * N_) / 128), 256>>>(
        ro, W_out, b_out, out, B_ * N_, V_, P_ / 2, V_, 0);
}